// round 2
// baseline (speedup 1.0000x reference)
#include <cuda_runtime.h>
#include <math.h>

#define NMAX 100000
#define EMAX 1600000
#define H 64
#define ED 32
#define NH 4
#define TOPK 10
#define MAXD 256

// scratch (static device globals -- no allocation)
__device__ float g_hW[NMAX * H];       // 25.6 MB
__device__ float g_s1[NMAX * NH];
__device__ float g_s2[NMAX * NH];
__device__ float g_score[EMAX];
__device__ int   g_deg[NMAX];
__device__ int   g_start[NMAX];
__device__ int   g_cursor[NMAX];
__device__ int   g_csr[EMAX];

__global__ void k_zero_deg(int n) {
    int i = blockIdx.x * blockDim.x + threadIdx.x;
    if (i < n) g_deg[i] = 0;
}

// ---------------------------------------------------------------------------
// K1: per-node precompute: hW = h @ whW + whb,  s1 = h @ aw[0:64],
//     s2 = h @ aw[64:128].  Warp per node, whW staged in shared.
// ---------------------------------------------------------------------------
__global__ void __launch_bounds__(256)
k_node_linear(const float* __restrict__ h,
              const float* __restrict__ whW,
              const float* __restrict__ whb,
              const float* __restrict__ attn_w,
              int n) {
    __shared__ float s_w[H * H];          // 16 KB
    __shared__ float s_b[H];
    __shared__ float s_aw[2 * H * NH];    // 2 KB
    __shared__ float s_h[8][H];           // 2 KB
    int tid = threadIdx.x;
    for (int i = tid; i < H * H; i += blockDim.x)   s_w[i] = whW[i];
    for (int i = tid; i < H; i += blockDim.x)        s_b[i] = whb[i];
    for (int i = tid; i < 2 * H * NH; i += blockDim.x) s_aw[i] = attn_w[i];
    __syncthreads();

    int lane = tid & 31, wl = tid >> 5;
    int warpG = (blockIdx.x * blockDim.x + tid) >> 5;
    int nwarps = (gridDim.x * blockDim.x) >> 5;

    for (int node = warpG; node < n; node += nwarps) {
        float h0 = h[(size_t)node * H + lane];
        float h1 = h[(size_t)node * H + 32 + lane];
        s_h[wl][lane] = h0;
        s_h[wl][32 + lane] = h1;
        __syncwarp();
        float a0 = 0.f, a1 = 0.f;
        #pragma unroll
        for (int k = 0; k < H; k++) {
            float hk = s_h[wl][k];
            a0 += hk * s_w[k * H + lane];
            a1 += hk * s_w[k * H + 32 + lane];
        }
        g_hW[(size_t)node * H + lane]      = a0 + s_b[lane];
        g_hW[(size_t)node * H + 32 + lane] = a1 + s_b[32 + lane];
        if (lane < 8) {
            int which = lane >> 2, head = lane & 3;
            const float* aw = s_aw + which * H * NH;
            float s = 0.f;
            #pragma unroll
            for (int k = 0; k < H; k++) s += s_h[wl][k] * aw[k * NH + head];
            if (which == 0) g_s1[node * NH + head] = s;
            else            g_s2[node * NH + head] = s;
        }
        __syncwarp();
    }
}

// ---------------------------------------------------------------------------
// K2: per-edge attention score + degree count.
//     Stages edge_attr tiles into shared with stride-33 padding (conflict-free).
// ---------------------------------------------------------------------------
__global__ void __launch_bounds__(256)
k_edge_score(const int* __restrict__ row,
             const int* __restrict__ col,
             const float* __restrict__ edge_attr,
             const float* __restrict__ attn_w,
             int e_cnt) {
    __shared__ float s_ea[256 * 33];   // 33.8 KB
    __shared__ float s_a3[ED * NH];
    int tid = threadIdx.x;
    for (int i = tid; i < ED * NH; i += blockDim.x)
        s_a3[i] = attn_w[2 * H * NH + i];

    int ntiles = (e_cnt + 255) / 256;
    for (int tile = blockIdx.x; tile < ntiles; tile += gridDim.x) {
        int base = tile * 256;
        int cnt = min(256, e_cnt - base);
        __syncthreads();
        for (int lin = tid; lin < cnt * ED; lin += blockDim.x) {
            int t = lin >> 5, k = lin & 31;
            s_ea[t * 33 + k] = edge_attr[(size_t)base * ED + lin];
        }
        __syncthreads();
        if (tid < cnt) {
            int e = base + tid;
            int r = row[e], c = col[e];
            float4 p1 = reinterpret_cast<const float4*>(g_s1)[r];
            float4 p2 = reinterpret_cast<const float4*>(g_s2)[c];
            float s3[NH] = {0.f, 0.f, 0.f, 0.f};
            #pragma unroll
            for (int k = 0; k < ED; k++) {
                float v = s_ea[tid * 33 + k];
                #pragma unroll
                for (int hd = 0; hd < NH; hd++)
                    s3[hd] += v * s_a3[k * NH + hd];
            }
            float t0 = p1.x + p2.x + s3[0];
            float t1 = p1.y + p2.y + s3[1];
            float t2 = p1.z + p2.z + s3[2];
            float t3 = p1.w + p2.w + s3[3];
            t0 = (t0 >= 0.f) ? t0 : 0.2f * t0;
            t1 = (t1 >= 0.f) ? t1 : 0.2f * t1;
            t2 = (t2 >= 0.f) ? t2 : 0.2f * t2;
            t3 = (t3 >= 0.f) ? t3 : 0.2f * t3;
            g_score[e] = 0.25f * (t0 + t1 + t2 + t3);
            atomicAdd(&g_deg[c], 1);
        }
    }
}

// ---------------------------------------------------------------------------
// K3: single-block exclusive scan of deg -> start, cursor. Tiles of 4096.
// ---------------------------------------------------------------------------
__global__ void __launch_bounds__(1024)
k_scan(int n) {
    __shared__ int s_wsum[32];
    __shared__ int s_carry;
    int t = threadIdx.x;
    int lane = t & 31, wid = t >> 5;
    if (t == 0) s_carry = 0;
    __syncthreads();
    for (int base = 0; base < n; base += 4096) {
        int idx0 = base + t * 4;
        int v0 = (idx0     < n) ? g_deg[idx0]     : 0;
        int v1 = (idx0 + 1 < n) ? g_deg[idx0 + 1] : 0;
        int v2 = (idx0 + 2 < n) ? g_deg[idx0 + 2] : 0;
        int v3 = (idx0 + 3 < n) ? g_deg[idx0 + 3] : 0;
        int tsum = v0 + v1 + v2 + v3;
        int x = tsum;
        #pragma unroll
        for (int off = 1; off < 32; off <<= 1) {
            int y = __shfl_up_sync(0xffffffffu, x, off);
            if (lane >= off) x += y;
        }
        if (lane == 31) s_wsum[wid] = x;
        __syncthreads();
        if (wid == 0) {
            int w = s_wsum[lane];
            #pragma unroll
            for (int off = 1; off < 32; off <<= 1) {
                int y = __shfl_up_sync(0xffffffffu, w, off);
                if (lane >= off) w += y;
            }
            s_wsum[lane] = w;
        }
        __syncthreads();
        int excl = s_carry + (wid ? s_wsum[wid - 1] : 0) + (x - tsum);
        if (idx0     < n) { g_start[idx0]     = excl; g_cursor[idx0]     = excl; } excl += v0;
        if (idx0 + 1 < n) { g_start[idx0 + 1] = excl; g_cursor[idx0 + 1] = excl; } excl += v1;
        if (idx0 + 2 < n) { g_start[idx0 + 2] = excl; g_cursor[idx0 + 2] = excl; } excl += v2;
        if (idx0 + 3 < n) { g_start[idx0 + 3] = excl; g_cursor[idx0 + 3] = excl; }
        __syncthreads();
        if (t == 0) s_carry += s_wsum[31];
        __syncthreads();
    }
}

// ---------------------------------------------------------------------------
// K4: scatter edge ids into CSR order.
// ---------------------------------------------------------------------------
__global__ void k_scatter(const int* __restrict__ col, int e_cnt) {
    int e = blockIdx.x * blockDim.x + threadIdx.x;
    if (e < e_cnt) {
        int c = col[e];
        int p = atomicAdd(&g_cursor[c], 1);
        g_csr[p] = e;
    }
}

// ---------------------------------------------------------------------------
// K5: warp-per-node: softmax, deterministic sort by edge id, top-k rank count
//     with (score desc, id asc) tie-break, message = relu(hW[row]+ea@weW+web),
//     3-group accumulate in registers, one coalesced row write. No out atomics.
// ---------------------------------------------------------------------------
__global__ void __launch_bounds__(256)
k_node_agg(const int* __restrict__ row,
           const float* __restrict__ edge_attr,
           const int* __restrict__ labels,
           const float* __restrict__ weW,
           const float* __restrict__ web,
           float* __restrict__ out,
           int n) {
    __shared__ float s_w[ED * H];        // 8 KB
    __shared__ float s_b[H];
    __shared__ float s_sc[8][MAXD];      // 8 KB
    __shared__ int   s_eid[8][MAXD];     // 8 KB
    __shared__ float s_at[8][MAXD];      // 8 KB
    int tid = threadIdx.x;
    for (int i = tid; i < ED * H; i += blockDim.x) s_w[i] = weW[i];
    for (int i = tid; i < H; i += blockDim.x)      s_b[i] = web[i];
    __syncthreads();

    int lane = tid & 31, wl = tid >> 5;
    int warpG = (blockIdx.x * blockDim.x + tid) >> 5;
    int nwarps = (gridDim.x * blockDim.x) >> 5;

    for (int node = warpG; node < n; node += nwarps) {
        int d = g_deg[node], st = g_start[node];
        float acc0 = 0.f, acc1 = 0.f, acc2 = 0.f, acc3 = 0.f, acc4 = 0.f, acc5 = 0.f;
        if (d > 0) {
            bool small = (d <= MAXD);
            float mx = -1e30f;
            for (int i = lane; i < d; i += 32) {
                int e = g_csr[st + i];
                float sc = g_score[e];
                if (small) { s_sc[wl][i] = sc; s_eid[wl][i] = e; }
                mx = fmaxf(mx, sc);
            }
            #pragma unroll
            for (int off = 16; off; off >>= 1)
                mx = fmaxf(mx, __shfl_xor_sync(0xffffffffu, mx, off));
            __syncwarp();

            if (small) {
                // odd-even transposition sort by edge id -> deterministic accumulation
                for (int p = 0; p < d; p++) {
                    for (int i = 2 * lane + (p & 1); i + 1 < d; i += 64) {
                        int e0 = s_eid[wl][i], e1 = s_eid[wl][i + 1];
                        if (e0 > e1) {
                            s_eid[wl][i] = e1; s_eid[wl][i + 1] = e0;
                            float tt = s_sc[wl][i];
                            s_sc[wl][i] = s_sc[wl][i + 1];
                            s_sc[wl][i + 1] = tt;
                        }
                    }
                    __syncwarp();
                }
            }

            float sum = 0.f;
            for (int i = lane; i < d; i += 32) {
                float sc = small ? s_sc[wl][i] : g_score[g_csr[st + i]];
                sum += expf(sc - mx);
            }
            #pragma unroll
            for (int off = 16; off; off >>= 1)
                sum += __shfl_xor_sync(0xffffffffu, sum, off);
            float invden = 1.f / sum;
            int lc = labels[node];

            if (small) {
                // lane-parallel rank count; final attn (0 if pruned) -> s_at
                for (int i = lane; i < d; i += 32) {
                    float sci = s_sc[wl][i];
                    int ei = s_eid[wl][i];
                    bool keep = true;
                    if (d > TOPK) {
                        int c = 0;
                        for (int j = 0; j < d; j++) {
                            float scj = s_sc[wl][j];
                            int ej = s_eid[wl][j];
                            c += (scj > sci) || (scj == sci && ej < ei);
                        }
                        keep = (c < TOPK);
                    }
                    s_at[wl][i] = keep ? expf(sci - mx) * invden : 0.f;
                }
                __syncwarp();
            }

            for (int i = 0; i < d; i++) {
                float a; int e;
                if (small) {
                    a = s_at[wl][i];
                    if (a == 0.f) continue;
                    e = s_eid[wl][i];
                } else {
                    e = g_csr[st + i];
                    float sci = g_score[e];
                    int c = 0;
                    for (int j = lane; j < d; j += 32) {
                        int ej = g_csr[st + j];
                        float scj = g_score[ej];
                        c += (scj > sci) || (scj == sci && ej < e);
                    }
                    #pragma unroll
                    for (int off = 16; off; off >>= 1)
                        c += __shfl_xor_sync(0xffffffffu, c, off);
                    if (c >= TOPK) continue;
                    a = expf(sci - mx) * invden;
                }
                int r = row[e];
                int lr = labels[r];
                int g = (lr < 0 || lc < 0) ? 2 : ((lr == lc) ? 0 : 1);
                float eav = edge_attr[(size_t)e * ED + lane];
                float v0 = g_hW[(size_t)r * H + lane];
                float v1 = g_hW[(size_t)r * H + 32 + lane];
                float w0 = 0.f, w1 = 0.f;
                #pragma unroll
                for (int k = 0; k < ED; k++) {
                    float b = __shfl_sync(0xffffffffu, eav, k);
                    w0 += b * s_w[k * H + lane];
                    w1 += b * s_w[k * H + 32 + lane];
                }
                float m0 = fmaxf(v0 + w0 + s_b[lane], 0.f);
                float m1 = fmaxf(v1 + w1 + s_b[32 + lane], 0.f);
                if (g == 0)      { acc0 += a * m0; acc1 += a * m1; }
                else if (g == 1) { acc2 += a * m0; acc3 += a * m1; }
                else             { acc4 += a * m0; acc5 += a * m1; }
            }
        }
        size_t ob = (size_t)node * (3 * H);
        out[ob + lane]            = acc0;
        out[ob + 32 + lane]       = acc1;
        out[ob + H + lane]        = acc2;
        out[ob + H + 32 + lane]   = acc3;
        out[ob + 2 * H + lane]      = acc4;
        out[ob + 2 * H + 32 + lane] = acc5;
    }
}

// ---------------------------------------------------------------------------
extern "C" void kernel_launch(void* const* d_in, const int* in_sizes, int n_in,
                              void* d_out, int out_size) {
    const float* h         = (const float*)d_in[0];
    const int*   edge_idx  = (const int*)  d_in[1];
    const float* edge_attr = (const float*)d_in[2];
    const int*   labels    = (const int*)  d_in[3];
    const float* attn_w    = (const float*)d_in[4];
    const float* whW       = (const float*)d_in[5];
    const float* whb       = (const float*)d_in[6];
    const float* weW       = (const float*)d_in[7];
    const float* web       = (const float*)d_in[8];
    float* out = (float*)d_out;

    int n = in_sizes[0] / H;
    int e = in_sizes[1] / 2;
    const int* row = edge_idx;
    const int* col = edge_idx + e;

    k_zero_deg<<<(n + 255) / 256, 256>>>(n);
    k_node_linear<<<1184, 256>>>(h, whW, whb, attn_w, n);
    k_edge_score<<<888, 256>>>(row, col, edge_attr, attn_w, e);
    k_scan<<<1, 1024>>>(n);
    k_scatter<<<(e + 255) / 256, 256>>>(col, e);
    k_node_agg<<<1036, 256>>>(row, edge_attr, labels, weW, web, out, n);
}

// round 3
// speedup vs baseline: 1.2371x; 1.2371x over previous
#include <cuda_runtime.h>
#include <math.h>

#define NMAX 100000
#define EMAX 1600000
#define H 64
#define ED 32
#define NH 4
#define TOPK 10
#define MAXD 96
#define KK 10

// scratch (static device globals -- no allocation)
__device__ float g_hW[NMAX * H];       // 25.6 MB
__device__ float g_s1[NMAX * NH];
__device__ float g_s2[NMAX * NH];
__device__ float g_score[EMAX];
__device__ int   g_deg[NMAX];
__device__ int   g_start[NMAX];
__device__ int   g_cursor[NMAX];
__device__ int   g_csr[EMAX];
__device__ int   g_bsum[64];

__global__ void k_zero_deg(int n) {
    int i = blockIdx.x * blockDim.x + threadIdx.x;
    if (i < n) g_deg[i] = 0;
}

__global__ void k_count(const int* __restrict__ col, int e_cnt) {
    int i = blockIdx.x * blockDim.x + threadIdx.x;
    if (i < e_cnt) atomicAdd(&g_deg[col[i]], 1);
}

// ---------------------------------------------------------------------------
// per-node precompute: hW = h @ whW + whb, s1 = h @ aw[0:64], s2 = h @ aw[64:128]
// ---------------------------------------------------------------------------
__global__ void __launch_bounds__(256)
k_node_linear(const float* __restrict__ h,
              const float* __restrict__ whW,
              const float* __restrict__ whb,
              const float* __restrict__ attn_w,
              int n) {
    __shared__ float s_w[H * H];
    __shared__ float s_b[H];
    __shared__ float s_aw[2 * H * NH];
    __shared__ float s_h[8][H];
    int tid = threadIdx.x;
    for (int i = tid; i < H * H; i += blockDim.x)      s_w[i] = whW[i];
    for (int i = tid; i < H; i += blockDim.x)          s_b[i] = whb[i];
    for (int i = tid; i < 2 * H * NH; i += blockDim.x) s_aw[i] = attn_w[i];
    __syncthreads();

    int lane = tid & 31, wl = tid >> 5;
    int warpG = (blockIdx.x * blockDim.x + tid) >> 5;
    int nwarps = (gridDim.x * blockDim.x) >> 5;

    for (int node = warpG; node < n; node += nwarps) {
        float h0 = h[(size_t)node * H + lane];
        float h1 = h[(size_t)node * H + 32 + lane];
        s_h[wl][lane] = h0;
        s_h[wl][32 + lane] = h1;
        __syncwarp();
        float a0 = 0.f, a1 = 0.f;
        #pragma unroll
        for (int k = 0; k < H; k++) {
            float hk = s_h[wl][k];
            a0 += hk * s_w[k * H + lane];
            a1 += hk * s_w[k * H + 32 + lane];
        }
        g_hW[(size_t)node * H + lane]      = a0 + s_b[lane];
        g_hW[(size_t)node * H + 32 + lane] = a1 + s_b[32 + lane];
        if (lane < 8) {
            int which = lane >> 2, head = lane & 3;
            const float* aw = s_aw + which * H * NH;
            float s = 0.f;
            #pragma unroll
            for (int k = 0; k < H; k++) s += s_h[wl][k] * aw[k * NH + head];
            if (which == 0) g_s1[node * NH + head] = s;
            else            g_s2[node * NH + head] = s;
        }
        __syncwarp();
    }
}

// ---------------------------------------------------------------------------
// multi-block scan of g_deg -> g_start/g_cursor. 2048 elems / block.
// ---------------------------------------------------------------------------
__global__ void __launch_bounds__(256)
k_scan_part(int n) {
    __shared__ int s_wsum[8];
    int b = blockIdx.x, t = threadIdx.x;
    int base = b * 2048 + t * 8;
    int v[8];
    #pragma unroll
    for (int j = 0; j < 8; j++) v[j] = (base + j < n) ? g_deg[base + j] : 0;
    int tsum = 0;
    #pragma unroll
    for (int j = 0; j < 8; j++) { int x = v[j]; v[j] = tsum; tsum += x; }
    int lane = t & 31, wid = t >> 5;
    int x = tsum;
    #pragma unroll
    for (int off = 1; off < 32; off <<= 1) {
        int y = __shfl_up_sync(0xffffffffu, x, off);
        if (lane >= off) x += y;
    }
    if (lane == 31) s_wsum[wid] = x;
    __syncthreads();
    if (t == 0) {
        int a = 0;
        #pragma unroll
        for (int w = 0; w < 8; w++) { int tt = s_wsum[w]; s_wsum[w] = a; a += tt; }
        g_bsum[b] = a;
    }
    __syncthreads();
    int excl = s_wsum[wid] + (x - tsum);
    #pragma unroll
    for (int j = 0; j < 8; j++)
        if (base + j < n) g_start[base + j] = excl + v[j];
}

__global__ void k_scan_top(int nb) {
    if (threadIdx.x == 0 && blockIdx.x == 0) {
        int a = 0;
        for (int i = 0; i < nb; i++) { int t = g_bsum[i]; g_bsum[i] = a; a += t; }
    }
}

__global__ void k_scan_add(int n) {
    int i = blockIdx.x * blockDim.x + threadIdx.x;
    if (i < n) {
        int s = g_start[i] + g_bsum[i >> 11];
        g_start[i] = s;
        g_cursor[i] = s;
    }
}

// ---------------------------------------------------------------------------
// fused per-edge attention score + CSR scatter.
// ---------------------------------------------------------------------------
__global__ void __launch_bounds__(256)
k_score_scatter(const int* __restrict__ row,
                const int* __restrict__ col,
                const float* __restrict__ edge_attr,
                const float* __restrict__ attn_w,
                int e_cnt) {
    __shared__ float s_a3[ED * NH];
    int tid = threadIdx.x;
    for (int i = tid; i < ED * NH; i += blockDim.x)
        s_a3[i] = attn_w[2 * H * NH + i];
    __syncthreads();

    int e = blockIdx.x * blockDim.x + tid;
    if (e >= e_cnt) return;
    int r = row[e], c = col[e];
    float4 p1 = reinterpret_cast<const float4*>(g_s1)[r];
    float4 p2 = reinterpret_cast<const float4*>(g_s2)[c];
    const float4* ea4 = reinterpret_cast<const float4*>(edge_attr + (size_t)e * ED);
    float s3[NH] = {0.f, 0.f, 0.f, 0.f};
    #pragma unroll
    for (int q = 0; q < 8; q++) {
        float4 v = ea4[q];
        int k = q * 4;
        #pragma unroll
        for (int hd = 0; hd < NH; hd++) {
            s3[hd] += v.x * s_a3[(k    ) * NH + hd];
            s3[hd] += v.y * s_a3[(k + 1) * NH + hd];
            s3[hd] += v.z * s_a3[(k + 2) * NH + hd];
            s3[hd] += v.w * s_a3[(k + 3) * NH + hd];
        }
    }
    float t0 = p1.x + p2.x + s3[0];
    float t1 = p1.y + p2.y + s3[1];
    float t2 = p1.z + p2.z + s3[2];
    float t3 = p1.w + p2.w + s3[3];
    t0 = (t0 >= 0.f) ? t0 : 0.2f * t0;
    t1 = (t1 >= 0.f) ? t1 : 0.2f * t1;
    t2 = (t2 >= 0.f) ? t2 : 0.2f * t2;
    t3 = (t3 >= 0.f) ? t3 : 0.2f * t3;
    g_score[e] = 0.25f * (t0 + t1 + t2 + t3);
    int p = atomicAdd(&g_cursor[c], 1);
    g_csr[p] = e;
}

// ---------------------------------------------------------------------------
// warp-per-node: sort by edge id (deterministic), softmax, top-k rank,
// COMPACT kept edges, batch-prefetch their edge_attr + hW rows (high MLP),
// then register-weight MAC loop. One coalesced 192-float row write per node.
// ---------------------------------------------------------------------------
__global__ void __launch_bounds__(256)
k_node_agg(const int* __restrict__ row,
           const float* __restrict__ edge_attr,
           const int* __restrict__ labels,
           const float* __restrict__ weW,
           const float* __restrict__ web,
           float* __restrict__ out,
           int n) {
    __shared__ float s_sc[8][MAXD];
    __shared__ int   s_eid[8][MAXD];
    __shared__ float s_ka[8][KK];
    __shared__ int   s_ke[8][KK];
    __shared__ float s_eav[8][KK][32];
    __shared__ float s_hw[8][KK][64];

    int tid = threadIdx.x;
    int lane = tid & 31, wl = tid >> 5;

    // weW resident in registers: lane holds column lane and lane+32
    float wlo[ED], whi[ED];
    #pragma unroll
    for (int k = 0; k < ED; k++) {
        wlo[k] = weW[k * H + lane];
        whi[k] = weW[k * H + 32 + lane];
    }
    float blo = web[lane], bhi = web[32 + lane];

    int warpG = (blockIdx.x * blockDim.x + tid) >> 5;
    int nwarps = (gridDim.x * blockDim.x) >> 5;

    for (int node = warpG; node < n; node += nwarps) {
        int d = g_deg[node], st = g_start[node];
        float acc0 = 0.f, acc1 = 0.f, acc2 = 0.f, acc3 = 0.f, acc4 = 0.f, acc5 = 0.f;
        if (d > 0 && d <= MAXD) {
            int lc = labels[node];
            for (int i = lane; i < d; i += 32) {
                int e = g_csr[st + i];
                s_eid[wl][i] = e;
                s_sc[wl][i] = g_score[e];
            }
            __syncwarp();
            // odd-even transposition sort by edge id -> canonical order
            for (int p = 0; p < d; p++) {
                for (int i = 2 * lane + (p & 1); i + 1 < d; i += 64) {
                    int e0 = s_eid[wl][i], e1 = s_eid[wl][i + 1];
                    if (e0 > e1) {
                        s_eid[wl][i] = e1; s_eid[wl][i + 1] = e0;
                        float tt = s_sc[wl][i];
                        s_sc[wl][i] = s_sc[wl][i + 1];
                        s_sc[wl][i + 1] = tt;
                    }
                }
                __syncwarp();
            }
            // max + sum(exp)
            float mx = -1e30f;
            for (int i = lane; i < d; i += 32) mx = fmaxf(mx, s_sc[wl][i]);
            #pragma unroll
            for (int off = 16; off; off >>= 1)
                mx = fmaxf(mx, __shfl_xor_sync(0xffffffffu, mx, off));
            float sum = 0.f;
            for (int i = lane; i < d; i += 32) sum += expf(s_sc[wl][i] - mx);
            #pragma unroll
            for (int off = 16; off; off >>= 1)
                sum += __shfl_xor_sync(0xffffffffu, sum, off);
            float invden = 1.f / sum;

            // rank (score desc, id asc) -> keep; compact kept edges via ballot
            int kk = 0;
            for (int base = 0; base < d; base += 32) {
                int i = base + lane;
                bool valid = (i < d);
                bool keep = false;
                float a = 0.f;
                if (valid) {
                    float sci = s_sc[wl][i];
                    int ei = s_eid[wl][i];
                    if (d <= TOPK) keep = true;
                    else {
                        int c = 0;
                        for (int j = 0; j < d; j++) {
                            float scj = s_sc[wl][j];
                            c += (scj > sci) || (scj == sci && s_eid[wl][j] < ei);
                        }
                        keep = (c < TOPK);
                    }
                    if (keep) a = expf(sci - mx) * invden;
                }
                unsigned bal = __ballot_sync(0xffffffffu, valid && keep);
                int pos = kk + __popc(bal & ((1u << lane) - 1u));
                if (valid && keep) {
                    s_ka[wl][pos] = a;
                    s_ke[wl][pos] = s_eid[wl][i];
                }
                kk += __popc(bal);
            }
            __syncwarp();

            // per-lane regs for kept edges (lane < kk)
            int e_reg = 0, r_reg = 0, g_reg = 2;
            float a_reg = 0.f;
            if (lane < kk) {
                e_reg = s_ke[wl][lane];
                a_reg = s_ka[wl][lane];
                r_reg = row[e_reg];
                int lr = labels[r_reg];
                g_reg = (lr < 0 || lc < 0) ? 2 : ((lr == lc) ? 0 : 1);
            }
            // batch prefetch (independent loads -> high MLP)
            for (int i = 0; i < kk; i++) {
                int e_i = __shfl_sync(0xffffffffu, e_reg, i);
                int r_i = __shfl_sync(0xffffffffu, r_reg, i);
                s_eav[wl][i][lane]    = edge_attr[(size_t)e_i * ED + lane];
                s_hw[wl][i][lane]     = g_hW[(size_t)r_i * H + lane];
                s_hw[wl][i][32 + lane] = g_hW[(size_t)r_i * H + 32 + lane];
            }
            __syncwarp();
            // MAC loop: pure FFMA + broadcast LDS
            for (int i = 0; i < kk; i++) {
                float a = __shfl_sync(0xffffffffu, a_reg, i);
                int g = __shfl_sync(0xffffffffu, g_reg, i);
                float w0 = 0.f, w1 = 0.f;
                #pragma unroll
                for (int k = 0; k < ED; k++) {
                    float bv = s_eav[wl][i][k];
                    w0 += bv * wlo[k];
                    w1 += bv * whi[k];
                }
                float m0 = fmaxf(s_hw[wl][i][lane] + w0 + blo, 0.f);
                float m1 = fmaxf(s_hw[wl][i][32 + lane] + w1 + bhi, 0.f);
                if (g == 0)      { acc0 += a * m0; acc1 += a * m1; }
                else if (g == 1) { acc2 += a * m0; acc3 += a * m1; }
                else             { acc4 += a * m0; acc5 += a * m1; }
            }
        } else if (d > MAXD) {
            // rare giant-degree fallback (global memory path)
            int lc = labels[node];
            float mx = -1e30f;
            for (int i = lane; i < d; i += 32) mx = fmaxf(mx, g_score[g_csr[st + i]]);
            #pragma unroll
            for (int off = 16; off; off >>= 1)
                mx = fmaxf(mx, __shfl_xor_sync(0xffffffffu, mx, off));
            float sum = 0.f;
            for (int i = lane; i < d; i += 32) sum += expf(g_score[g_csr[st + i]] - mx);
            #pragma unroll
            for (int off = 16; off; off >>= 1)
                sum += __shfl_xor_sync(0xffffffffu, sum, off);
            float invden = 1.f / sum;
            for (int i = 0; i < d; i++) {
                int e = g_csr[st + i];
                float sci = g_score[e];
                int c = 0;
                for (int j = lane; j < d; j += 32) {
                    int ej = g_csr[st + j];
                    float scj = g_score[ej];
                    c += (scj > sci) || (scj == sci && ej < e);
                }
                #pragma unroll
                for (int off = 16; off; off >>= 1)
                    c += __shfl_xor_sync(0xffffffffu, c, off);
                if (c >= TOPK) continue;
                float a = expf(sci - mx) * invden;
                int r = row[e];
                int lr = labels[r];
                int g = (lr < 0 || lc < 0) ? 2 : ((lr == lc) ? 0 : 1);
                float eav = edge_attr[(size_t)e * ED + lane];
                float v0 = g_hW[(size_t)r * H + lane];
                float v1 = g_hW[(size_t)r * H + 32 + lane];
                float w0 = 0.f, w1 = 0.f;
                #pragma unroll
                for (int k = 0; k < ED; k++) {
                    float b = __shfl_sync(0xffffffffu, eav, k);
                    w0 += b * wlo[k];
                    w1 += b * whi[k];
                }
                float m0 = fmaxf(v0 + w0 + blo, 0.f);
                float m1 = fmaxf(v1 + w1 + bhi, 0.f);
                if (g == 0)      { acc0 += a * m0; acc1 += a * m1; }
                else if (g == 1) { acc2 += a * m0; acc3 += a * m1; }
                else             { acc4 += a * m0; acc5 += a * m1; }
            }
        }
        size_t ob = (size_t)node * (3 * H);
        out[ob + lane]              = acc0;
        out[ob + 32 + lane]         = acc1;
        out[ob + H + lane]          = acc2;
        out[ob + H + 32 + lane]     = acc3;
        out[ob + 2 * H + lane]      = acc4;
        out[ob + 2 * H + 32 + lane] = acc5;
    }
}

// ---------------------------------------------------------------------------
extern "C" void kernel_launch(void* const* d_in, const int* in_sizes, int n_in,
                              void* d_out, int out_size) {
    const float* h         = (const float*)d_in[0];
    const int*   edge_idx  = (const int*)  d_in[1];
    const float* edge_attr = (const float*)d_in[2];
    const int*   labels    = (const int*)  d_in[3];
    const float* attn_w    = (const float*)d_in[4];
    const float* whW       = (const float*)d_in[5];
    const float* whb       = (const float*)d_in[6];
    const float* weW       = (const float*)d_in[7];
    const float* web       = (const float*)d_in[8];
    float* out = (float*)d_out;

    int n = in_sizes[0] / H;
    int e = in_sizes[1] / 2;
    const int* row = edge_idx;
    const int* col = edge_idx + e;

    int nb = (n + 2047) / 2048;

    k_zero_deg<<<(n + 255) / 256, 256>>>(n);
    k_count<<<(e + 255) / 256, 256>>>(col, e);
    k_node_linear<<<1184, 256>>>(h, whW, whb, attn_w, n);
    k_scan_part<<<nb, 256>>>(n);
    k_scan_top<<<1, 32>>>(nb);
    k_scan_add<<<(n + 255) / 256, 256>>>(n);
    k_score_scatter<<<(e + 255) / 256, 256>>>(row, col, edge_attr, attn_w, e);
    k_node_agg<<<592, 256>>>(row, edge_attr, labels, weW, web, out, n);
}

// round 4
// speedup vs baseline: 1.5024x; 1.2145x over previous
#include <cuda_runtime.h>
#include <math.h>

#define NMAX 100000
#define EMAX 1600000
#define H 64
#define ED 32
#define NH 4
#define TOPK 10
#define MAXD 96
#define KK 10

// scratch (static device globals -- no allocation)
__device__ float g_hW[NMAX * H];       // 25.6 MB
__device__ float g_s1[NMAX * NH];
__device__ float g_s2[NMAX * NH];
__device__ float g_score[EMAX];
__device__ int   g_deg[NMAX];
__device__ int   g_start[NMAX];
__device__ int   g_cursor[NMAX];
__device__ int   g_csr[EMAX];
__device__ int   g_bsum[64];

__global__ void k_zero_deg(int n) {
    int i = blockIdx.x * blockDim.x + threadIdx.x;
    if (i < n) g_deg[i] = 0;
}

__global__ void k_count(const int* __restrict__ col, int e_cnt) {
    int i = blockIdx.x * blockDim.x + threadIdx.x;
    if (i < e_cnt) atomicAdd(&g_deg[col[i]], 1);
}

// ---------------------------------------------------------------------------
// per-node precompute: hW = h @ whW + whb, s1 = h @ aw[0:64], s2 = h @ aw[64:128]
// Weights register-resident; h broadcast via shfl (no shared in hot loop).
// ---------------------------------------------------------------------------
__global__ void __launch_bounds__(256)
k_node_linear(const float* __restrict__ h,
              const float* __restrict__ whW,
              const float* __restrict__ whb,
              const float* __restrict__ attn_w,
              int n) {
    __shared__ float s_aw[2 * H * NH];
    int tid = threadIdx.x;
    int lane = tid & 31;
    for (int i = tid; i < 2 * H * NH; i += blockDim.x) s_aw[i] = attn_w[i];

    // whW columns (lane, lane+32) in registers
    float wlo[H], whi[H];
    #pragma unroll
    for (int k = 0; k < H; k++) {
        wlo[k] = whW[k * H + lane];
        whi[k] = whW[k * H + 32 + lane];
    }
    float blo = whb[lane], bhi = whb[32 + lane];
    __syncthreads();

    int warpG = (blockIdx.x * blockDim.x + tid) >> 5;
    int nwarps = (gridDim.x * blockDim.x) >> 5;

    for (int node = warpG; node < n; node += nwarps) {
        float h0 = h[(size_t)node * H + lane];
        float h1 = h[(size_t)node * H + 32 + lane];
        float a0 = 0.f, a1 = 0.f;
        float sA = 0.f, sB = 0.f;   // partial attn projections (lane < 8 uses)
        #pragma unroll
        for (int k = 0; k < 32; k++) {
            float hk = __shfl_sync(0xffffffffu, h0, k);
            a0 += hk * wlo[k];
            a1 += hk * whi[k];
        }
        #pragma unroll
        for (int k = 0; k < 32; k++) {
            float hk = __shfl_sync(0xffffffffu, h1, k);
            a0 += hk * wlo[32 + k];
            a1 += hk * whi[32 + k];
        }
        g_hW[(size_t)node * H + lane]      = a0 + blo;
        g_hW[(size_t)node * H + 32 + lane] = a1 + bhi;
        // attn projections: 8 lanes each compute one (which, head) dot product
        // using shared h staged via shfl-free path: read h directly (L1 hit).
        if (lane < 8) {
            int which = lane >> 2, head = lane & 3;
            const float* aw = s_aw + which * H * NH;
            const float* hp = h + (size_t)node * H;
            float s = 0.f;
            #pragma unroll
            for (int k = 0; k < H; k++) s += hp[k] * aw[k * NH + head];
            if (which == 0) g_s1[node * NH + head] = s;
            else            g_s2[node * NH + head] = s;
        }
        (void)sA; (void)sB;
    }
}

// ---------------------------------------------------------------------------
// multi-block scan of g_deg -> g_start/g_cursor. 2048 elems / block.
// ---------------------------------------------------------------------------
__global__ void __launch_bounds__(256)
k_scan_part(int n) {
    __shared__ int s_wsum[8];
    int b = blockIdx.x, t = threadIdx.x;
    int base = b * 2048 + t * 8;
    int v[8];
    #pragma unroll
    for (int j = 0; j < 8; j++) v[j] = (base + j < n) ? g_deg[base + j] : 0;
    int tsum = 0;
    #pragma unroll
    for (int j = 0; j < 8; j++) { int x = v[j]; v[j] = tsum; tsum += x; }
    int lane = t & 31, wid = t >> 5;
    int x = tsum;
    #pragma unroll
    for (int off = 1; off < 32; off <<= 1) {
        int y = __shfl_up_sync(0xffffffffu, x, off);
        if (lane >= off) x += y;
    }
    if (lane == 31) s_wsum[wid] = x;
    __syncthreads();
    if (t == 0) {
        int a = 0;
        #pragma unroll
        for (int w = 0; w < 8; w++) { int tt = s_wsum[w]; s_wsum[w] = a; a += tt; }
        g_bsum[b] = a;
    }
    __syncthreads();
    int excl = s_wsum[wid] + (x - tsum);
    #pragma unroll
    for (int j = 0; j < 8; j++)
        if (base + j < n) g_start[base + j] = excl + v[j];
}

__global__ void k_scan_top(int nb) {
    if (threadIdx.x == 0 && blockIdx.x == 0) {
        int a = 0;
        for (int i = 0; i < nb; i++) { int t = g_bsum[i]; g_bsum[i] = a; a += t; }
    }
}

__global__ void k_scan_add(int n) {
    int i = blockIdx.x * blockDim.x + threadIdx.x;
    if (i < n) {
        int s = g_start[i] + g_bsum[i >> 11];
        g_start[i] = s;
        g_cursor[i] = s;
    }
}

// ---------------------------------------------------------------------------
// fused per-edge attention score + CSR scatter.
// ---------------------------------------------------------------------------
__global__ void __launch_bounds__(256)
k_score_scatter(const int* __restrict__ row,
                const int* __restrict__ col,
                const float* __restrict__ edge_attr,
                const float* __restrict__ attn_w,
                int e_cnt) {
    __shared__ float s_a3[ED * NH];
    int tid = threadIdx.x;
    for (int i = tid; i < ED * NH; i += blockDim.x)
        s_a3[i] = attn_w[2 * H * NH + i];
    __syncthreads();

    int e = blockIdx.x * blockDim.x + tid;
    if (e >= e_cnt) return;
    int r = row[e], c = col[e];
    float4 p1 = reinterpret_cast<const float4*>(g_s1)[r];
    float4 p2 = reinterpret_cast<const float4*>(g_s2)[c];
    const float4* ea4 = reinterpret_cast<const float4*>(edge_attr + (size_t)e * ED);
    float s3[NH] = {0.f, 0.f, 0.f, 0.f};
    #pragma unroll
    for (int q = 0; q < 8; q++) {
        float4 v = ea4[q];
        int k = q * 4;
        #pragma unroll
        for (int hd = 0; hd < NH; hd++) {
            s3[hd] += v.x * s_a3[(k    ) * NH + hd];
            s3[hd] += v.y * s_a3[(k + 1) * NH + hd];
            s3[hd] += v.z * s_a3[(k + 2) * NH + hd];
            s3[hd] += v.w * s_a3[(k + 3) * NH + hd];
        }
    }
    float t0 = p1.x + p2.x + s3[0];
    float t1 = p1.y + p2.y + s3[1];
    float t2 = p1.z + p2.z + s3[2];
    float t3 = p1.w + p2.w + s3[3];
    t0 = (t0 >= 0.f) ? t0 : 0.2f * t0;
    t1 = (t1 >= 0.f) ? t1 : 0.2f * t1;
    t2 = (t2 >= 0.f) ? t2 : 0.2f * t2;
    t3 = (t3 >= 0.f) ? t3 : 0.2f * t3;
    g_score[e] = 0.25f * (t0 + t1 + t2 + t3);
    int p = atomicAdd(&g_cursor[c], 1);
    g_csr[p] = e;
}

// ---------------------------------------------------------------------------
// warp-per-node aggregation.
//  d<=32 : fully register path — warp bitonic sort by edge id (deterministic),
//          shfl softmax + rank count, ballot compaction. NO shared, NO syncs.
//  32<d<=96 : shared odd-even path (rare).
//  d>96  : global fallback (≈never).
// Then: batch-prefetch kept edge_attr/hW rows into shared, register-weight
// MAC loop, one coalesced 192-float row write. No output atomics.
// ---------------------------------------------------------------------------
__global__ void __launch_bounds__(256)
k_node_agg(const int* __restrict__ row,
           const float* __restrict__ edge_attr,
           const int* __restrict__ labels,
           const float* __restrict__ weW,
           const float* __restrict__ web,
           float* __restrict__ out,
           int n) {
    __shared__ float s_sc[8][MAXD];
    __shared__ int   s_eid[8][MAXD];
    __shared__ float s_ka[8][KK];
    __shared__ int   s_ke[8][KK];
    __shared__ float s_eav[8][KK][32];
    __shared__ float s_hw[8][KK][64];

    int tid = threadIdx.x;
    int lane = tid & 31, wl = tid >> 5;

    float wlo[ED], whi[ED];
    #pragma unroll
    for (int k = 0; k < ED; k++) {
        wlo[k] = weW[k * H + lane];
        whi[k] = weW[k * H + 32 + lane];
    }
    float blo = web[lane], bhi = web[32 + lane];

    int warpG = (blockIdx.x * blockDim.x + tid) >> 5;
    int nwarps = (gridDim.x * blockDim.x) >> 5;

    for (int node = warpG; node < n; node += nwarps) {
        int d = g_deg[node], st = g_start[node];
        float acc0 = 0.f, acc1 = 0.f, acc2 = 0.f, acc3 = 0.f, acc4 = 0.f, acc5 = 0.f;
        int kk = 0;
        if (d > 0 && d <= 32) {
            // -------- register fast path --------
            bool valid = lane < d;
            int   e  = valid ? g_csr[st + lane] : 0x7FFFFFFF;
            float sc = valid ? g_score[e] : 0.f;
            // warp bitonic sort ascending by edge id (payload sc)
            #pragma unroll
            for (int k2 = 2; k2 <= 32; k2 <<= 1) {
                #pragma unroll
                for (int j = k2 >> 1; j > 0; j >>= 1) {
                    int   pe  = __shfl_xor_sync(0xffffffffu, e,  j);
                    float psc = __shfl_xor_sync(0xffffffffu, sc, j);
                    bool keepMin = ((lane & k2) == 0) == ((lane & j) == 0);
                    if ((e < pe) != keepMin) { e = pe; sc = psc; }
                }
            }
            valid = lane < d;   // sorted ascending: real edges now in lanes 0..d-1
            // softmax max (fixed shfl tree -> deterministic)
            float mx = valid ? sc : -1e30f;
            #pragma unroll
            for (int off = 16; off; off >>= 1)
                mx = fmaxf(mx, __shfl_xor_sync(0xffffffffu, mx, off));
            float ex = valid ? expf(sc - mx) : 0.f;
            float sum = ex;
            #pragma unroll
            for (int off = 16; off; off >>= 1)
                sum += __shfl_xor_sync(0xffffffffu, sum, off);
            float invden = 1.f / sum;
            // rank (score desc, id asc)
            int cnt = 0;
            if (d > TOPK) {
                for (int j = 0; j < d; j++) {
                    float scj = __shfl_sync(0xffffffffu, sc, j);
                    int   ej  = __shfl_sync(0xffffffffu, e,  j);
                    cnt += (scj > sc) || (scj == sc && ej < e);
                }
            }
            bool keep = valid && (cnt < TOPK);
            unsigned bal = __ballot_sync(0xffffffffu, keep);
            kk = __popc(bal);
            int pos = __popc(bal & ((1u << lane) - 1u));
            if (keep) {
                s_ka[wl][pos] = ex * invden;
                s_ke[wl][pos] = e;
            }
            __syncwarp();
        } else if (d > 32 && d <= MAXD) {
            // -------- shared path (rare) --------
            for (int i = lane; i < d; i += 32) {
                int e = g_csr[st + i];
                s_eid[wl][i] = e;
                s_sc[wl][i] = g_score[e];
            }
            __syncwarp();
            for (int p = 0; p < d; p++) {
                for (int i = 2 * lane + (p & 1); i + 1 < d; i += 64) {
                    int e0 = s_eid[wl][i], e1 = s_eid[wl][i + 1];
                    if (e0 > e1) {
                        s_eid[wl][i] = e1; s_eid[wl][i + 1] = e0;
                        float tt = s_sc[wl][i];
                        s_sc[wl][i] = s_sc[wl][i + 1];
                        s_sc[wl][i + 1] = tt;
                    }
                }
                __syncwarp();
            }
            float mx = -1e30f;
            for (int i = lane; i < d; i += 32) mx = fmaxf(mx, s_sc[wl][i]);
            #pragma unroll
            for (int off = 16; off; off >>= 1)
                mx = fmaxf(mx, __shfl_xor_sync(0xffffffffu, mx, off));
            float sum = 0.f;
            for (int i = lane; i < d; i += 32) sum += expf(s_sc[wl][i] - mx);
            #pragma unroll
            for (int off = 16; off; off >>= 1)
                sum += __shfl_xor_sync(0xffffffffu, sum, off);
            float invden = 1.f / sum;
            for (int base = 0; base < d; base += 32) {
                int i = base + lane;
                bool valid = (i < d);
                bool keep = false;
                float a = 0.f;
                if (valid) {
                    float sci = s_sc[wl][i];
                    int ei = s_eid[wl][i];
                    int c = 0;
                    for (int j = 0; j < d; j++) {
                        float scj = s_sc[wl][j];
                        c += (scj > sci) || (scj == sci && s_eid[wl][j] < ei);
                    }
                    keep = (c < TOPK);
                    if (keep) a = expf(sci - mx) * invden;
                }
                unsigned bal = __ballot_sync(0xffffffffu, valid && keep);
                int pos = kk + __popc(bal & ((1u << lane) - 1u));
                if (valid && keep) {
                    s_ka[wl][pos] = a;
                    s_ke[wl][pos] = s_eid[wl][i];
                }
                kk += __popc(bal);
            }
            __syncwarp();
        } else if (d > MAXD) {
            // -------- giant fallback (effectively never) --------
            int lc = labels[node];
            float mx = -1e30f;
            for (int i = lane; i < d; i += 32) mx = fmaxf(mx, g_score[g_csr[st + i]]);
            #pragma unroll
            for (int off = 16; off; off >>= 1)
                mx = fmaxf(mx, __shfl_xor_sync(0xffffffffu, mx, off));
            float sum = 0.f;
            for (int i = lane; i < d; i += 32) sum += expf(g_score[g_csr[st + i]] - mx);
            #pragma unroll
            for (int off = 16; off; off >>= 1)
                sum += __shfl_xor_sync(0xffffffffu, sum, off);
            float invden = 1.f / sum;
            for (int i = 0; i < d; i++) {
                int e = g_csr[st + i];
                float sci = g_score[e];
                int c = 0;
                for (int j = lane; j < d; j += 32) {
                    int ej = g_csr[st + j];
                    float scj = g_score[ej];
                    c += (scj > sci) || (scj == sci && ej < e);
                }
                #pragma unroll
                for (int off = 16; off; off >>= 1)
                    c += __shfl_xor_sync(0xffffffffu, c, off);
                if (c >= TOPK) continue;
                float a = expf(sci - mx) * invden;
                int r = row[e];
                int lr = labels[r];
                int g = (lr < 0 || lc < 0) ? 2 : ((lr == lc) ? 0 : 1);
                float eav = edge_attr[(size_t)e * ED + lane];
                float v0 = g_hW[(size_t)r * H + lane];
                float v1 = g_hW[(size_t)r * H + 32 + lane];
                float w0 = 0.f, w1 = 0.f;
                #pragma unroll
                for (int k = 0; k < ED; k++) {
                    float b = __shfl_sync(0xffffffffu, eav, k);
                    w0 += b * wlo[k];
                    w1 += b * whi[k];
                }
                float m0 = fmaxf(v0 + w0 + blo, 0.f);
                float m1 = fmaxf(v1 + w1 + bhi, 0.f);
                if (g == 0)      { acc0 += a * m0; acc1 += a * m1; }
                else if (g == 1) { acc2 += a * m0; acc3 += a * m1; }
                else             { acc4 += a * m0; acc5 += a * m1; }
            }
        }

        if (kk > 0) {
            int lc = labels[node];
            int e_reg = 0, r_reg = 0, g_reg = 2;
            float a_reg = 0.f;
            if (lane < kk) {
                e_reg = s_ke[wl][lane];
                a_reg = s_ka[wl][lane];
                r_reg = row[e_reg];
                int lr = labels[r_reg];
                g_reg = (lr < 0 || lc < 0) ? 2 : ((lr == lc) ? 0 : 1);
            }
            // batch prefetch (independent loads -> high MLP)
            for (int i = 0; i < kk; i++) {
                int e_i = __shfl_sync(0xffffffffu, e_reg, i);
                int r_i = __shfl_sync(0xffffffffu, r_reg, i);
                s_eav[wl][i][lane]     = edge_attr[(size_t)e_i * ED + lane];
                s_hw[wl][i][lane]      = g_hW[(size_t)r_i * H + lane];
                s_hw[wl][i][32 + lane] = g_hW[(size_t)r_i * H + 32 + lane];
            }
            __syncwarp();
            // MAC loop: pure FFMA + broadcast LDS
            for (int i = 0; i < kk; i++) {
                float a = __shfl_sync(0xffffffffu, a_reg, i);
                int g = __shfl_sync(0xffffffffu, g_reg, i);
                float w0 = 0.f, w1 = 0.f;
                #pragma unroll
                for (int k = 0; k < ED; k++) {
                    float bv = s_eav[wl][i][k];
                    w0 += bv * wlo[k];
                    w1 += bv * whi[k];
                }
                float m0 = fmaxf(s_hw[wl][i][lane] + w0 + blo, 0.f);
                float m1 = fmaxf(s_hw[wl][i][32 + lane] + w1 + bhi, 0.f);
                if (g == 0)      { acc0 += a * m0; acc1 += a * m1; }
                else if (g == 1) { acc2 += a * m0; acc3 += a * m1; }
                else             { acc4 += a * m0; acc5 += a * m1; }
            }
        }

        size_t ob = (size_t)node * (3 * H);
        out[ob + lane]              = acc0;
        out[ob + 32 + lane]         = acc1;
        out[ob + H + lane]          = acc2;
        out[ob + H + 32 + lane]     = acc3;
        out[ob + 2 * H + lane]      = acc4;
        out[ob + 2 * H + 32 + lane] = acc5;
    }
}

// ---------------------------------------------------------------------------
extern "C" void kernel_launch(void* const* d_in, const int* in_sizes, int n_in,
                              void* d_out, int out_size) {
    const float* h         = (const float*)d_in[0];
    const int*   edge_idx  = (const int*)  d_in[1];
    const float* edge_attr = (const float*)d_in[2];
    const int*   labels    = (const int*)  d_in[3];
    const float* attn_w    = (const float*)d_in[4];
    const float* whW       = (const float*)d_in[5];
    const float* whb       = (const float*)d_in[6];
    const float* weW       = (const float*)d_in[7];
    const float* web       = (const float*)d_in[8];
    float* out = (float*)d_out;

    int n = in_sizes[0] / H;
    int e = in_sizes[1] / 2;
    const int* row = edge_idx;
    const int* col = edge_idx + e;

    int nb = (n + 2047) / 2048;

    k_zero_deg<<<(n + 255) / 256, 256>>>(n);
    k_count<<<(e + 255) / 256, 256>>>(col, e);
    k_node_linear<<<592, 256>>>(h, whW, whb, attn_w, n);
    k_scan_part<<<nb, 256>>>(n);
    k_scan_top<<<1, 32>>>(nb);
    k_scan_add<<<(n + 255) / 256, 256>>>(n);
    k_score_scatter<<<(e + 255) / 256, 256>>>(row, col, edge_attr, attn_w, e);
    k_node_agg<<<592, 256>>>(row, edge_attr, labels, weW, web, out, n);
}